// round 15
// baseline (speedup 1.0000x reference)
#include <cuda_runtime.h>
#include <cuda_bf16.h>
#include <cuda_fp16.h>
#include <cstdint>

// B=4, N=4096 tok/batch, d_qk=128, d_v=256.
// Reference reshapes are flat reinterprets of TOKEN-major projection buffers:
// pq[c][n] = q_flat[c*4096+n]  =>  attention channel c = tok>>5 (qk) / tok>>4 (v),
// attention pos n mixes (tok & 31/15) with proj channel pc.
//
// Round-15 (vs 249.0us):
//  * Flash is at the legacy-mma.sync pipe floor (188us) / wave-balance
//    (216 = 188/0.865 for 256 CTAs on 148 SMs). Fix: 4-way SPLIT-K:
//    grid (64,4,4) = 1024 CTAs -> 6.92/SM -> 98.8% balance. Each CTA does
//    1024 keys, writes fp16 unnormalized partial O + per-row (l, m).
//  * Distributed fixup: last split CTA per job (atomic counter) combines the
//    4 partials (exp(m_i - M) weights) and writes y = gamma*O/L + x, so the
//    combine traffic overlaps other CTAs' MMA.
//  * gemm / preps unchanged.

#define NTOK  4096
#define DQK   128
#define DV    256
#define BATCH 4
#define BM    64
#define BN    32
#define NSPLIT 4
#define NKT_SP 32     // key tiles per split
#define LDQF  72      // Q image row stride (q dim), [ch=128][q=64]
#define LDK   40      // K image row stride (key dim), [ch=128][key=32]
#define LDV   40      // V image row stride (key dim), [ch=256][key=32]

// -------- device scratch (no allocations allowed) --------
__device__ __align__(16) __half g_xhi[4 * BATCH * NTOK * 72];
__device__ __align__(16) __half g_whi[4 * 512 * 72];
__device__ float g_bias[512];
__device__ __align__(16) __half g_qimg[BATCH * 64 * 128 * LDQF];    // [b,qt][ch][q]
__device__ __align__(16) __half g_kimg[BATCH * 128 * 128 * LDK];    // [b,kt][ch][key]
__device__ __align__(16) __half g_vimg[BATCH * 128 * DV * LDV];     // [b,kt][ch][key]
// split-K partials: 1024 partials x [256 ch][64 q] fp16, + l/m rows + counter
__device__ __align__(16) __half g_pO[1024 * 16384];                 // 33.5 MB
__device__ float g_plm[1024 * 128];   // [p][0..63 l | 64..127 m]
__device__ int   g_cnt[256];          // per-job arrival counter (memset to 0)

// ---------------- wrappers ----------------
__device__ __forceinline__ uint32_t smem_u32(const void* p) {
    uint32_t a;
    asm("{ .reg .u64 t; cvta.to.shared.u64 t, %1; cvt.u32.u64 %0, t; }" : "=r"(a) : "l"(p));
    return a;
}
__device__ __forceinline__ void ldsm_x4(uint32_t* r, uint32_t saddr) {
    asm volatile("ldmatrix.sync.aligned.m8n8.x4.shared.b16 {%0,%1,%2,%3}, [%4];"
        : "=r"(r[0]), "=r"(r[1]), "=r"(r[2]), "=r"(r[3]) : "r"(saddr));
}
__device__ __forceinline__ void ldsm_x4_t(uint32_t* r, uint32_t saddr) {
    asm volatile("ldmatrix.sync.aligned.m8n8.x4.trans.shared.b16 {%0,%1,%2,%3}, [%4];"
        : "=r"(r[0]), "=r"(r[1]), "=r"(r[2]), "=r"(r[3]) : "r"(saddr));
}
__device__ __forceinline__ void mma_f16(float* d, const uint32_t* a, const uint32_t* b) {
    asm volatile("mma.sync.aligned.m16n8k16.row.col.f32.f16.f16.f32 "
        "{%0,%1,%2,%3}, {%4,%5,%6,%7}, {%8,%9}, {%0,%1,%2,%3};"
        : "+f"(d[0]), "+f"(d[1]), "+f"(d[2]), "+f"(d[3])
        : "r"(a[0]), "r"(a[1]), "r"(a[2]), "r"(a[3]), "r"(b[0]), "r"(b[1]));
}
__device__ __forceinline__ uint32_t packh2(__half x, __half y) {
    __half2 t; t.x = x; t.y = y;
    return *reinterpret_cast<uint32_t*>(&t);
}
__device__ __forceinline__ void bulk_cp(uint32_t dst, const void* src,
                                        uint32_t bytes, uint32_t mbar) {
    asm volatile(
        "cp.async.bulk.shared::cta.global.mbarrier::complete_tx::bytes [%0], [%1], %2, [%3];"
        :: "r"(dst), "l"(src), "r"(bytes), "r"(mbar) : "memory");
}
__device__ __forceinline__ void expect_tx(uint32_t mbar, uint32_t bytes) {
    asm volatile("mbarrier.arrive.expect_tx.shared.b64 _, [%0], %1;"
        :: "r"(mbar), "r"(bytes) : "memory");
}
#define MBARRIER_INIT(mbar, cnt) \
    asm volatile("mbarrier.init.shared.b64 [%0], %1;" :: "r"((uint32_t)(mbar)), "r"((uint32_t)(cnt)) : "memory")
#define MBARRIER_WAIT_PARITY(mbar, parity) do { \
    uint32_t _m = (uint32_t)(mbar); uint32_t _p = (uint32_t)(parity); uint32_t _d; \
    asm volatile("{\n\t.reg .pred p;\n\t" \
        "mbarrier.try_wait.parity.acquire.cta.shared::cta.b64 p, [%1], %2;\n\t" \
        "selp.b32 %0, 1, 0, p;\n\t}" : "=r"(_d) : "r"(_m), "r"(_p) : "memory"); \
    if (!_d) { \
        asm volatile("{\n\t.reg .pred P1;\n\t" \
            "WL_%=:\n\t" \
            "mbarrier.try_wait.parity.acquire.cta.shared::cta.b64 P1, [%0], %1, 0x989680;\n\t" \
            "@P1 bra.uni WD_%=;\n\t" \
            "bra.uni WL_%=;\n\t" \
            "WD_%=:\n\t}" :: "r"(_m), "r"(_p) : "memory"); \
    } } while (0)

// ---------------- prep_x: x fp32 -> fp16 padded k-step image ----------------
__global__ __launch_bounds__(256) void prep_x_kernel(const float* __restrict__ x) {
    size_t i = (size_t)blockIdx.x * 256 + threadIdx.x;
    int c = (int)(i & 255);
    size_t n = i >> 8;
    size_t off = ((size_t)(c >> 6) * (BATCH * NTOK) + n) * 72 + (c & 63);
    g_xhi[off] = __float2half_rn(x[i]);
}

// ---------------- prep_w: transpose weights -> fp16, concat bias ----------------
__global__ __launch_bounds__(256) void prep_w_kernel(
    const float* __restrict__ Wq, const float* __restrict__ bq,
    const float* __restrict__ Wk, const float* __restrict__ bk,
    const float* __restrict__ Wv, const float* __restrict__ bv)
{
    const int d = blockIdx.x, c = threadIdx.x;
    float w;
    if (d < 128)      w = Wq[c * 128 + d];
    else if (d < 256) w = Wk[c * 128 + (d - 128)];
    else              w = Wv[c * 256 + (d - 256)];
    size_t off = ((size_t)(c >> 6) * 512 + d) * 72 + (c & 63);
    g_whi[off] = __float2half_rn(w);
    if (c == 0)
        g_bias[d] = (d < 128) ? bq[d] : (d < 256) ? bk[d - 128] : bv[d - 256];
}

// ---------------- projection GEMM, epilogue writes flash images ----------------
#define GLDA 72
#define GSAHI 0
#define GSBHI 9216
#define GMBAR 36864
#define GSM_BYTES 36896

__global__ __launch_bounds__(256, 2) void gemm_tensor_kernel() {
    extern __shared__ __half sg[];
    const uint32_t sb = smem_u32(sg);
    const uint32_t mbar = sb + GMBAR;
    const int t = threadIdx.x, lane = t & 31, wid = t >> 5;
    const int nt = blockIdx.x;
    const int m0 = blockIdx.y * 128;
    const int n0 = nt * 128;
    const int lg = lane >> 3, lr = lane & 7;
    const uint32_t a_base = (uint32_t)((16 * wid + lr + (lg & 1) * 8) * GLDA + (lg >> 1) * 8);
    const uint32_t b_base = (uint32_t)(lr * GLDA + lg * 8);

    if (t == 0) MBARRIER_INIT(mbar, 1);
    __syncthreads();

    float acc[16][4];
#pragma unroll
    for (int nf = 0; nf < 16; nf++)
#pragma unroll
        for (int e = 0; e < 4; e++) acc[nf][e] = 0.f;

    for (int kb = 0; kb < 4; kb++) {
        if (t == 0) {
            expect_tx(mbar, 2 * 18432);
            const size_t aoff = ((size_t)kb * (BATCH * NTOK) + m0) * 72;
            const size_t boff = ((size_t)kb * 512 + n0) * 72;
            bulk_cp(sb + 2 * GSAHI, g_xhi + aoff, 18432, mbar);
            bulk_cp(sb + 2 * GSBHI, g_whi + boff, 18432, mbar);
        }
        MBARRIER_WAIT_PARITY(mbar, kb & 1);
#pragma unroll
        for (int kkp = 0; kkp < 2; kkp++) {
            uint32_t qh0[4], qh1[4];
            ldsm_x4(qh0, sb + 2 * (GSAHI + a_base + 32 * kkp));
            ldsm_x4(qh1, sb + 2 * (GSAHI + a_base + 32 * kkp + 16));
#pragma unroll
            for (int nf = 0; nf < 16; nf++) {
                uint32_t bh[4];
                ldsm_x4(bh, sb + 2 * (GSBHI + b_base + nf * 8 * GLDA + 32 * kkp));
                mma_f16(acc[nf], qh0, bh);
                mma_f16(acc[nf], qh1, bh + 2);
            }
        }
        __syncthreads();
    }

    // ---- epilogue: +bias, round fp16, write flash images directly ----
    const int lq = 2 * (lane & 3);
    const int rr0 = m0 + 16 * wid + (lane >> 2);
#pragma unroll
    for (int rowp = 0; rowp < 2; rowp++) {
        const int tok = rr0 + 8 * rowp;
        const int b   = tok >> 12;
        const int tt  = tok & 4095;
        if (nt == 0) {
            const int qtb = (tt & 31) * 2;
            const int ch  = tt >> 5;
#pragma unroll
            for (int nf = 0; nf < 16; nf++) {
                const int pc = nf * 8 + lq;
                const float b0 = g_bias[n0 + pc], b1 = g_bias[n0 + pc + 1];
                __half* dst = g_qimg
                    + ((size_t)(b * 64 + qtb + (nf >> 3)) * 128 + ch) * LDQF
                    + (pc & 63);
                *(uint32_t*)dst = packh2(
                    __float2half_rn(acc[nf][2 * rowp] + b0),
                    __float2half_rn(acc[nf][2 * rowp + 1] + b1));
            }
        } else if (nt == 1) {
            const int ktb = (tt & 31) * 4;
            const int ch  = tt >> 5;
#pragma unroll
            for (int nf = 0; nf < 16; nf++) {
                const int pc = nf * 8 + lq;
                const float b0 = g_bias[n0 + pc], b1 = g_bias[n0 + pc + 1];
                __half* dst = g_kimg
                    + ((size_t)(b * 128 + ktb + (nf >> 2)) * 128 + ch) * LDK
                    + ((nf & 3) * 8 + lq);
                *(uint32_t*)dst = packh2(
                    __float2half_rn(acc[nf][2 * rowp] + b0),
                    __float2half_rn(acc[nf][2 * rowp + 1] + b1));
            }
        } else {
            const int ktb = (tt & 15) * 8 + (nt - 2) * 4;
            const int ch  = tt >> 4;
#pragma unroll
            for (int nf = 0; nf < 16; nf++) {
                const int pc = nf * 8 + lq;
                const float b0 = g_bias[n0 + pc], b1 = g_bias[n0 + pc + 1];
                __half* dst = g_vimg
                    + ((size_t)(b * 128 + ktb + (nf >> 2)) * DV + ch) * LDV
                    + ((nf & 3) * 8 + lq);
                *(uint32_t*)dst = packh2(
                    __float2half_rn(acc[nf][2 * rowp] + b0),
                    __float2half_rn(acc[nf][2 * rowp + 1] + b1));
            }
        }
    }
}

// ---------------- flash kernel (split-K, BM=64, 128 thr, 2 CTAs/SM) ----------------
// smem (halves): Q[128ch x 72]@0 (9216), K bufs @9216 (2x5120),
// V bufs @19456 (2x10240) -> 39936 halves = 79872 B.
// bytes: mbars @79872 (16B) + done flag @79888, lrow @79936 (64f),
// mrow @80192 (64f), sw @80448 (256f). epilogue Osm reuses [0, 256*68*4).
#define SQHI 0
#define SK0  9216
#define SV0  19456
#define KBUF 5120
#define VBUF 10240
#define MBAR_OFF 79872
#define DONE_OFF 79888
#define LROW_OFF 79936
#define MROW_OFF 80192
#define SW_OFF   80448
#define OSM_LD 68
#define SM_BYTES 81472
#define TILE_BYTES (2 * KBUF + 2 * VBUF)   // 30720 bytes

__global__ __launch_bounds__(128, 2) void flash_kernel(
    const float* __restrict__ xin, const float* __restrict__ gamma_p,
    float* __restrict__ yout)
{
    extern __shared__ __half sm[];
    const uint32_t sb = smem_u32(sm);
    const uint32_t mb0 = sb + MBAR_OFF, mb1 = sb + MBAR_OFF + 8;
    const int t = threadIdx.x, lane = t & 31, wid = t >> 5;   // wid < 4
    const int qt = blockIdx.x, b = blockIdx.y, sp = blockIdx.z;
    const int job = b * 64 + qt;
    const int p   = job * NSPLIT + sp;
    const int n0  = qt * BM;
    const int lg = lane >> 3, lr = lane & 7;
    const uint32_t qa_base = (uint32_t)((lr + (lg >> 1) * 8) * LDQF
                                        + 16 * wid + (lg & 1) * 8);
    const uint32_t kb_base = (uint32_t)((lr + lg * 8) * LDK);
    const uint32_t vb_base = (uint32_t)(lr * LDV + lg * 8);

    const __half* kimg = g_kimg + ((size_t)b * 128 + sp * NKT_SP) * (size_t)(128 * LDK);
    const __half* vimg = g_vimg + ((size_t)b * 128 + sp * NKT_SP) * (size_t)(DV * LDV);

    if (t == 0) { MBARRIER_INIT(mb0, 1); MBARRIER_INIT(mb1, 1); }
    __syncthreads();
    if (t == 0) {
        expect_tx(mb0, TILE_BYTES + 2 * 128 * LDQF);
        bulk_cp(sb, g_qimg + (size_t)(b * 64 + qt) * (128 * LDQF),
                2 * 128 * LDQF, mb0);
        bulk_cp(sb + 2 * SK0, kimg, 2 * KBUF, mb0);
        bulk_cp(sb + 2 * SV0, vimg, 2 * VBUF, mb0);
        expect_tx(mb1, TILE_BYTES);
        bulk_cp(sb + 2 * (SK0 + KBUF), kimg + KBUF, 2 * KBUF, mb1);
        bulk_cp(sb + 2 * (SV0 + VBUF), vimg + VBUF, 2 * VBUF, mb1);
    }

    float oacc[32][4];
#pragma unroll
    for (int nf = 0; nf < 32; nf++)
#pragma unroll
        for (int e = 0; e < 4; e++) oacc[nf][e] = 0.f;
    float lsum0 = 0.f, lsum1 = 0.f;
    float m0 = -1e30f, m1 = -1e30f;

    for (int kt = 0; kt < NKT_SP; kt++) {
        const int buf = kt & 1;
        MBARRIER_WAIT_PARITY(buf ? mb1 : mb0, (kt >> 1) & 1);

        const uint32_t khi = SK0 + buf * KBUF;
        const uint32_t vhi = SV0 + buf * VBUF;

        // ---- S = Q K^T (single-term fp16, trans operand loads) ----
        float sa[4][4], sc[4][4];
#pragma unroll
        for (int nn = 0; nn < 4; nn++)
#pragma unroll
            for (int e = 0; e < 4; e++) { sa[nn][e] = 0.f; sc[nn][e] = 0.f; }
#pragma unroll
        for (int kkp = 0; kkp < 4; kkp++) {
            uint32_t qh0[4], qh1[4];
            ldsm_x4_t(qh0, sb + 2 * (SQHI + qa_base + (32 * kkp) * LDQF));
            ldsm_x4_t(qh1, sb + 2 * (SQHI + qa_base + (32 * kkp + 16) * LDQF));
#pragma unroll
            for (int nn = 0; nn < 4; nn++) {
                uint32_t kh[4];
                ldsm_x4_t(kh, sb + 2 * (khi + kb_base + (32 * kkp) * LDK + nn * 8));
                mma_f16(sa[nn], qh0, kh);
                mma_f16(sc[nn], qh1, kh + 2);
            }
        }

        // ---- online softmax with running max ----
        float svv[4][4];
#pragma unroll
        for (int nn = 0; nn < 4; nn++)
#pragma unroll
            for (int e = 0; e < 4; e++) svv[nn][e] = sa[nn][e] + sc[nn][e];

        float tm0 = -1e30f, tm1 = -1e30f;
#pragma unroll
        for (int nn = 0; nn < 4; nn++) {
            tm0 = fmaxf(tm0, fmaxf(svv[nn][0], svv[nn][1]));
            tm1 = fmaxf(tm1, fmaxf(svv[nn][2], svv[nn][3]));
        }
        tm0 = fmaxf(tm0, __shfl_xor_sync(0xffffffffu, tm0, 1));
        tm0 = fmaxf(tm0, __shfl_xor_sync(0xffffffffu, tm0, 2));
        tm1 = fmaxf(tm1, __shfl_xor_sync(0xffffffffu, tm1, 1));
        tm1 = fmaxf(tm1, __shfl_xor_sync(0xffffffffu, tm1, 2));
        const float mn0 = fmaxf(m0, tm0), mn1 = fmaxf(m1, tm1);
        const float sc0 = __expf(m0 - mn0), sc1 = __expf(m1 - mn1);
        m0 = mn0; m1 = mn1;
        if (sc0 < 1.f) {
            lsum0 *= sc0;
#pragma unroll
            for (int nf = 0; nf < 32; nf++) { oacc[nf][0] *= sc0; oacc[nf][1] *= sc0; }
        }
        if (sc1 < 1.f) {
            lsum1 *= sc1;
#pragma unroll
            for (int nf = 0; nf < 32; nf++) { oacc[nf][2] *= sc1; oacc[nf][3] *= sc1; }
        }

        uint32_t phi[2][4];
#pragma unroll
        for (int kk = 0; kk < 2; kk++)
#pragma unroll
            for (int half = 0; half < 2; half++) {
                const float* pp = svv[2 * kk + half];
                __half h0 = __float2half_rn(__expf(pp[0] - mn0));
                __half h1 = __float2half_rn(__expf(pp[1] - mn0));
                __half h2 = __float2half_rn(__expf(pp[2] - mn1));
                __half h3 = __float2half_rn(__expf(pp[3] - mn1));
                phi[kk][2 * half + 0] = packh2(h0, h1);
                phi[kk][2 * half + 1] = packh2(h2, h3);
                lsum0 += __half2float(h0) + __half2float(h1);
                lsum1 += __half2float(h2) + __half2float(h3);
            }

        // ---- O += P V (single-term fp16), all 256 channels ----
#pragma unroll
        for (int nf = 0; nf < 32; nf++) {
            uint32_t vh[4];
            ldsm_x4(vh, sb + 2 * (vhi + vb_base + nf * 8 * LDV));
            mma_f16(oacc[nf], phi[0], vh);
            mma_f16(oacc[nf], phi[1], vh + 2);
        }
        __syncthreads();
        if (t == 0 && kt + 2 < NKT_SP) {
            const uint32_t mb = buf ? mb1 : mb0;
            expect_tx(mb, TILE_BYTES);
            bulk_cp(sb + 2 * khi, kimg + (size_t)(kt + 2) * KBUF, 2 * KBUF, mb);
            bulk_cp(sb + 2 * vhi, vimg + (size_t)(kt + 2) * VBUF, 2 * VBUF, mb);
        }
    }

    // ---- partial epilogue: transpose O, write fp16 partial + (l, m) ----
    lsum0 += __shfl_xor_sync(0xffffffffu, lsum0, 1);
    lsum0 += __shfl_xor_sync(0xffffffffu, lsum0, 2);
    lsum1 += __shfl_xor_sync(0xffffffffu, lsum1, 1);
    lsum1 += __shfl_xor_sync(0xffffffffu, lsum1, 2);
    float* Osm  = (float*)sm;
    float* lrow = (float*)((char*)sm + LROW_OFF);
    float* mrow = (float*)((char*)sm + MROW_OFF);
    const int rloc = 16 * wid + (lane >> 2);          // 0..63
    if ((lane & 3) == 0) {
        lrow[rloc] = lsum0; lrow[rloc + 8] = lsum1;
        mrow[rloc] = m0;    mrow[rloc + 8] = m1;
    }
#pragma unroll
    for (int nf = 0; nf < 32; nf++) {
        const int c = nf * 8 + 2 * (lane & 3);
        Osm[c * OSM_LD + rloc] = oacc[nf][0];
        Osm[(c + 1) * OSM_LD + rloc] = oacc[nf][1];
        Osm[c * OSM_LD + rloc + 8] = oacc[nf][2];
        Osm[(c + 1) * OSM_LD + rloc + 8] = oacc[nf][3];
    }
    __syncthreads();
    // write partial O (fp16) coalesced: [ch][q]
    {
        __half* pdst = g_pO + (size_t)p * 16384;
        for (int i = t; i < 256 * 16; i += 128) {
            const int c = i >> 4, nn = (i & 15) << 2;
            float4 o = *(float4*)&Osm[c * OSM_LD + nn];
            *(uint32_t*)(pdst + c * 64 + nn)     = packh2(__float2half_rn(o.x), __float2half_rn(o.y));
            *(uint32_t*)(pdst + c * 64 + nn + 2) = packh2(__float2half_rn(o.z), __float2half_rn(o.w));
        }
        if (t < 64) {
            g_plm[(size_t)p * 128 + t]      = lrow[t];
            g_plm[(size_t)p * 128 + 64 + t] = mrow[t];
        }
    }
    __threadfence();
    __syncthreads();
    int* done = (int*)((char*)sm + DONE_OFF);
    if (t == 0) *done = atomicAdd(&g_cnt[job], 1);
    __syncthreads();
    if (*done != NSPLIT - 1) return;

    // ---- fixup (last split CTA of this job): combine 4 partials ----
    float* sw = (float*)((char*)sm + SW_OFF);   // [4][64] scales
    if (t < 64) {
        float mm[NSPLIT], ll[NSPLIT];
        float M = -1e30f;
#pragma unroll
        for (int i = 0; i < NSPLIT; i++) {
            mm[i] = g_plm[(size_t)(job * NSPLIT + i) * 128 + 64 + t];
            ll[i] = g_plm[(size_t)(job * NSPLIT + i) * 128 + t];
            M = fmaxf(M, mm[i]);
        }
        float L = 0.f, wv[NSPLIT];
#pragma unroll
        for (int i = 0; i < NSPLIT; i++) { wv[i] = __expf(mm[i] - M); L += ll[i] * wv[i]; }
        const float s = gamma_p[0] / L;
#pragma unroll
        for (int i = 0; i < NSPLIT; i++) sw[i * 64 + t] = wv[i] * s;
    }
    __syncthreads();
    const float* xb = xin  + (size_t)b * DV * NTOK;
    float*       yb = yout + (size_t)b * DV * NTOK;
    const __half2* pO2 = (const __half2*)g_pO;
    for (int j = 0; j < 64; j++) {
        const int e2 = t + 128 * j;             // 0..8191 half2 over [ch][q2]
        const int ch = e2 >> 5, q = (e2 & 31) * 2;
        float acc0 = 0.f, acc1 = 0.f;
#pragma unroll
        for (int i = 0; i < NSPLIT; i++) {
            __half2 h = pO2[(size_t)(job * NSPLIT + i) * 8192 + e2];
            acc0 += __low2float(h)  * sw[i * 64 + q];
            acc1 += __high2float(h) * sw[i * 64 + q + 1];
        }
        const size_t gi = (size_t)ch * NTOK + n0 + q;
        float2 xv = *(const float2*)(xb + gi);
        float2 y; y.x = acc0 + xv.x; y.y = acc1 + xv.y;
        *(float2*)(yb + gi) = y;
    }
}

// ---------------- launch ----------------
extern "C" void kernel_launch(void* const* d_in, const int* in_sizes, int n_in,
                              void* d_out, int out_size)
{
    const float* x     = (const float*)d_in[0];
    const float* Wq    = (const float*)d_in[1];
    const float* bq    = (const float*)d_in[2];
    const float* Wk    = (const float*)d_in[3];
    const float* bk    = (const float*)d_in[4];
    const float* Wv    = (const float*)d_in[5];
    const float* bv    = (const float*)d_in[6];
    const float* gamma = (const float*)d_in[7];
    float* out = (float*)d_out;

    void* cnt_ptr;
    cudaGetSymbolAddress(&cnt_ptr, g_cnt);
    cudaMemsetAsync(cnt_ptr, 0, 256 * sizeof(int));

    prep_x_kernel<<<BATCH * NTOK, 256>>>(x);
    prep_w_kernel<<<512, 256>>>(Wq, bq, Wk, bk, Wv, bv);

    cudaFuncSetAttribute(gemm_tensor_kernel,
                         cudaFuncAttributeMaxDynamicSharedMemorySize, GSM_BYTES);
    gemm_tensor_kernel<<<dim3(4, BATCH * NTOK / 128), 256, GSM_BYTES>>>();

    cudaFuncSetAttribute(flash_kernel,
                         cudaFuncAttributeMaxDynamicSharedMemorySize, SM_BYTES);
    flash_kernel<<<dim3(64, BATCH, NSPLIT), 128, SM_BYTES>>>(x, gamma, out);
}